// round 15
// baseline (speedup 1.0000x reference)
#include <cuda_runtime.h>
#include <cuda_fp16.h>
#include <math.h>
#include <stdint.h>

#define BB 2
#define SS 2048
#define DD 2048
#define H 16
#define HK 8
#define HD 128
#define MTOT (BB*SS)   // 4096

// ---------------- scratch (allocation-free: device globals) ----------------
__device__ float g_q[(size_t)MTOT * H * HD];
__device__ float g_k[(size_t)MTOT * HK * HD];
__device__ float g_v[(size_t)MTOT * HK * HD];
__device__ float g_cos[SS * 64];
__device__ float g_sin[SS * 64];

__device__ __align__(16) __half g_x16[(size_t)MTOT * DD];
__device__ __align__(16) __half g_wq16[(size_t)(H*HD) * DD];
__device__ __align__(16) __half g_wk16[(size_t)(HK*HD) * DD];
__device__ __align__(16) __half g_wv16[(size_t)(HK*HD) * DD];
__device__ __align__(16) __half g_wo16[(size_t)DD * (H*HD)];
__device__ __align__(16) __half g_o16[(size_t)MTOT * (H*HD)];
__device__ __align__(16) __half g_q16[(size_t)MTOT * H * HD];
__device__ __align__(16) __half g_k16[(size_t)MTOT * HK * HD];
__device__ __align__(16) __half g_vt16[(size_t)MTOT * HK * HD];  // [b][hk][d][tok]

// ---------------- asm helpers ----------------------------------------------
__device__ __forceinline__ uint32_t smem_u32(const void* p) {
    uint32_t a;
    asm("{ .reg .u64 t; cvta.to.shared.u64 t, %1; cvt.u32.u64 %0, t; }" : "=r"(a) : "l"(p));
    return a;
}

#define CP_ASYNC16(dst, src) \
    asm volatile("cp.async.cg.shared.global [%0], [%1], 16;" :: "r"(dst), "l"(src))
#define CP_COMMIT() asm volatile("cp.async.commit_group;" ::: "memory")
#define CP_WAIT2()  asm volatile("cp.async.wait_group 2;" ::: "memory")
#define CP_WAIT1()  asm volatile("cp.async.wait_group 1;" ::: "memory")
#define CP_WAIT0()  asm volatile("cp.async.wait_group 0;" ::: "memory")

__device__ __forceinline__ void ldsm4(uint32_t* r, uint32_t a) {
    asm volatile("ldmatrix.sync.aligned.m8n8.x4.shared.b16 {%0,%1,%2,%3}, [%4];"
        : "=r"(r[0]), "=r"(r[1]), "=r"(r[2]), "=r"(r[3]) : "r"(a));
}
__device__ __forceinline__ void ldsm2(uint32_t* r, uint32_t a) {
    asm volatile("ldmatrix.sync.aligned.m8n8.x2.shared.b16 {%0,%1}, [%2];"
        : "=r"(r[0]), "=r"(r[1]) : "r"(a));
}
__device__ __forceinline__ void mma_f16(float* c, const uint32_t* a, const uint32_t* b) {
    asm volatile("mma.sync.aligned.m16n8k16.row.col.f32.f16.f16.f32 "
        "{%0,%1,%2,%3}, {%4,%5,%6,%7}, {%8,%9}, {%0,%1,%2,%3};"
        : "+f"(c[0]), "+f"(c[1]), "+f"(c[2]), "+f"(c[3])
        : "r"(a[0]), "r"(a[1]), "r"(a[2]), "r"(a[3]), "r"(b[0]), "r"(b[1]));
}

__device__ __forceinline__ uint32_t pack_hf2(float a, float b) {
    __half2 t;
    t.x = __float2half_rn(a);
    t.y = __float2half_rn(b);
    return *(uint32_t*)&t;
}

// --------- single-pass fp16 GEMM body: C = A * B^T -------------------------
// A (M,K) fp16, W (N,K) fp16, C (M,N) fp32. CTA 128x128, BK=32, 256 thr.
// 4-stage cp.async pipeline, smem stride 40 halves (conflict-free ldmatrix).
#define SST 40
#define MATB (128 * SST * 2)      // 10240 B per matrix
#define STG1 (2 * MATB)           // 20480 B per stage (A, B)
#define GEMM_SMEM (4 * STG1)      // 81920 B  -> 2 CTAs/SM

__device__ __forceinline__ void gemm_load_stage(
    uint32_t sbase, int slot,
    const __half* __restrict__ A, const __half* __restrict__ B,
    int m0, int n0, int K, int k0, int t)
{
    uint32_t st = sbase + slot * STG1;
    const __half* gp[2] = { A + (size_t)m0 * K + k0, B + (size_t)n0 * K + k0 };
    #pragma unroll
    for (int mat = 0; mat < 2; mat++) {
        #pragma unroll
        for (int h = 0; h < 2; h++) {
            int c = t + h * 256;          // 0..511
            int row = c >> 2, col16 = c & 3;
            uint32_t dst = st + mat * MATB + row * (SST*2) + col16 * 16;
            const __half* src = gp[mat] + (size_t)row * K + col16 * 8;
            CP_ASYNC16(dst, src);
        }
    }
}

__device__ __forceinline__ void gemm_body(
    uint32_t sb, const __half* __restrict__ A, const __half* __restrict__ B,
    float* __restrict__ C, int N, int K, int m0, int n0, int t)
{
    const int lane = t & 31, wid = t >> 5;
    const int warp_m = wid >> 2;
    const int warp_n = wid & 3;
    const int niter = K >> 5;

    float acc[4][4][4];
    #pragma unroll
    for (int i = 0; i < 4; i++)
        #pragma unroll
        for (int j = 0; j < 4; j++)
            acc[i][j][0] = acc[i][j][1] = acc[i][j][2] = acc[i][j][3] = 0.f;

    #pragma unroll
    for (int s = 0; s < 3; s++) {
        if (s < niter) gemm_load_stage(sb, s, A, B, m0, n0, K, s * 32, t);
        CP_COMMIT();
    }

    const int arow = warp_m * 64 + (lane & 15);
    const int acolh = (lane >> 4) * 8;
    const int l2 = lane & 15;
    const int brow = warp_n * 32 + (l2 & 7);
    const int bcolh = (l2 >> 3) * 8;

    for (int it = 0; it < niter; it++) {
        int ps = it + 3;
        if (ps < niter)
            gemm_load_stage(sb, ps & 3, A, B, m0, n0, K, ps * 32, t);
        CP_COMMIT();
        CP_WAIT2();
        __syncthreads();

        uint32_t st = sb + (it & 3) * STG1;
        #pragma unroll
        for (int ks = 0; ks < 2; ks++) {
            uint32_t af[4][4], bf[4][2];
            #pragma unroll
            for (int mt = 0; mt < 4; mt++) {
                uint32_t off = ((arow + mt * 16) * SST + ks * 16 + acolh) * 2;
                ldsm4(af[mt], st + off);
            }
            #pragma unroll
            for (int nt = 0; nt < 4; nt++) {
                uint32_t off = ((brow + nt * 8) * SST + ks * 16 + bcolh) * 2;
                ldsm2(bf[nt], st + MATB + off);
            }
            #pragma unroll
            for (int mt = 0; mt < 4; mt++)
                #pragma unroll
                for (int nt = 0; nt < 4; nt++)
                    mma_f16(acc[mt][nt], af[mt], bf[nt]);
        }
        __syncthreads();
    }

    const int r0 = lane >> 2, c0 = (lane & 3) * 2;
    #pragma unroll
    for (int mt = 0; mt < 4; mt++) {
        #pragma unroll
        for (int nt = 0; nt < 4; nt++) {
            int row = m0 + warp_m * 64 + mt * 16 + r0;
            int col = n0 + warp_n * 32 + nt * 8 + c0;
            *(float2*)(C + (size_t)row * N + col) =
                make_float2(acc[mt][nt][0], acc[mt][nt][1]);
            *(float2*)(C + (size_t)(row + 8) * N + col) =
                make_float2(acc[mt][nt][2], acc[mt][nt][3]);
        }
    }
}

// out-projection (single GEMM)
__global__ __launch_bounds__(256, 2)
void gemm_f16(const __half* __restrict__ A, const __half* __restrict__ B,
              float* __restrict__ C, int N, int K)
{
    extern __shared__ char smem[];
    gemm_body(smem_u32(smem), A, B, C, N, K,
              blockIdx.y * 128, blockIdx.x * 128, threadIdx.x);
}

// fused QKV: one launch, 1024 CTAs decode {Q:512, K:256, V:256}
__global__ __launch_bounds__(256, 2)
void gemm_qkv(const __half* __restrict__ x16,
              const __half* __restrict__ wq16, const __half* __restrict__ wk16,
              const __half* __restrict__ wv16,
              float* __restrict__ q, float* __restrict__ k, float* __restrict__ v)
{
    extern __shared__ char smem[];
    int bid = blockIdx.x;
    const __half* B;
    float* C;
    int N, m0, n0;
    if (bid < 512) {                 // Q: 16 n-tiles x 32 m-tiles
        B = wq16; C = q; N = H*HD;
        n0 = (bid & 15) * 128; m0 = (bid >> 4) * 128;
    } else if (bid < 768) {          // K: 8 x 32
        int b2 = bid - 512;
        B = wk16; C = k; N = HK*HD;
        n0 = (b2 & 7) * 128; m0 = (b2 >> 3) * 128;
    } else {                         // V: 8 x 32
        int b2 = bid - 768;
        B = wv16; C = v; N = HK*HD;
        n0 = (b2 & 7) * 128; m0 = (b2 >> 3) * 128;
    }
    gemm_body(smem_u32(smem), x16, B, C, N, DD, m0, n0, threadIdx.x);
}

// ------- fused fp32 -> fp16 conversion of all 5 tensors in one launch ------
#define N4_X  (MTOT*DD/4)          // 2097152
#define N4_WQ (H*HD*DD/4)          // 1048576
#define N4_WK (HK*HD*DD/4)         //  524288
#define N4_WV (HK*HD*DD/4)         //  524288
#define N4_WO (DD*H*HD/4)          // 1048576
#define N4_TOT (N4_X + N4_WQ + N4_WK + N4_WV + N4_WO)

__global__ __launch_bounds__(256)
void conv_all(const float* __restrict__ x,  const float* __restrict__ wq,
              const float* __restrict__ wk, const float* __restrict__ wv,
              const float* __restrict__ wo,
              __half* __restrict__ x16,  __half* __restrict__ wq16,
              __half* __restrict__ wk16, __half* __restrict__ wv16,
              __half* __restrict__ wo16)
{
    int i = blockIdx.x * blockDim.x + threadIdx.x;
    if (i >= N4_TOT) return;
    const float* src;
    __half* dst;
    int j = i;
    if (j < N4_X)                        { src = x;  dst = x16; }
    else if ((j -= N4_X)  < N4_WQ)       { src = wq; dst = wq16; }
    else if ((j -= N4_WQ) < N4_WK)       { src = wk; dst = wk16; }
    else if ((j -= N4_WK) < N4_WV)       { src = wv; dst = wv16; }
    else { j -= N4_WV;                     src = wo; dst = wo16; }
    float4 vv = ((const float4*)src)[j];
    __half2 p0, p1;
    p0.x = __float2half_rn(vv.x); p0.y = __float2half_rn(vv.y);
    p1.x = __float2half_rn(vv.z); p1.y = __float2half_rn(vv.w);
    ((__half2*)(dst + (size_t)j * 4))[0] = p0;
    ((__half2*)(dst + (size_t)j * 4))[1] = p1;
}

// ---------------- RoPE table ------------------------------------------------
__global__ void rope_table()
{
    int s = blockIdx.x;
    int j = threadIdx.x;
    double invd = pow(1.0e6, -(double)j / 64.0);
    float  ang  = (float)s * (float)invd;
    float  c, sn;
    sincosf(ang, &sn, &c);
    g_cos[s*64 + j] = c;
    g_sin[s*64 + j] = sn;
}

// -------- fused RMSNorm + RoPE -> single fp16 ------------------------------
__global__ __launch_bounds__(256)
void norm_rope_f16(const float* __restrict__ buf, __half* __restrict__ outh,
                   const float* __restrict__ w, int nheads)
{
    int gw   = (blockIdx.x * blockDim.x + threadIdx.x) >> 5;
    int lane = threadIdx.x & 31;
    int m = gw / nheads;
    int h = gw - m * nheads;
    int s = m & (SS - 1);

    size_t base = ((size_t)m * nheads + h) * HD + lane * 4;
    float4 v = *(const float4*)(buf + base);
    float ss = v.x*v.x + v.y*v.y + v.z*v.z + v.w*v.w;
    #pragma unroll
    for (int o = 16; o; o >>= 1) ss += __shfl_xor_sync(0xffffffffu, ss, o);
    float r = rsqrtf(ss * (1.f/128.f) + 1e-6f);

    const float4 wv = *(const float4*)(w + lane*4);
    v.x *= r * wv.x; v.y *= r * wv.y; v.z *= r * wv.z; v.w *= r * wv.w;

    float4 pr;
    pr.x = __shfl_xor_sync(0xffffffffu, v.x, 16);
    pr.y = __shfl_xor_sync(0xffffffffu, v.y, 16);
    pr.z = __shfl_xor_sync(0xffffffffu, v.z, 16);
    pr.w = __shfl_xor_sync(0xffffffffu, v.w, 16);

    int jbase = (lane & 15) * 4;
    const float* cb = g_cos + s*64 + jbase;
    const float* sb = g_sin + s*64 + jbase;
    float sgn = (lane < 16) ? -1.f : 1.f;

    float o0 = v.x * cb[0] + sgn * pr.x * sb[0];
    float o1 = v.y * cb[1] + sgn * pr.y * sb[1];
    float o2 = v.z * cb[2] + sgn * pr.z * sb[2];
    float o3 = v.w * cb[3] + sgn * pr.w * sb[3];

    __half2 hp0, hp1;
    hp0.x = __float2half_rn(o0); hp0.y = __float2half_rn(o1);
    hp1.x = __float2half_rn(o2); hp1.y = __float2half_rn(o3);
    ((__half2*)(outh + base))[0] = hp0;
    ((__half2*)(outh + base))[1] = hp1;
}

// ---- V transpose: [tok][hk][d] fp32 -> [b][hk][d][tok] fp16 ---------------
__global__ __launch_bounds__(256)
void transp_v16(const float* __restrict__ v, __half* __restrict__ vt)
{
    __shared__ float tile[32][33];
    int t = threadIdx.x;
    int tx = t & 31, ty = t >> 5;
    int tok0 = blockIdx.x * 32, d0 = blockIdx.y * 32;
    int bh = blockIdx.z;
    int b = bh >> 3, hk = bh & 7;

    #pragma unroll
    for (int r = 0; r < 4; r++) {
        int tok = ty + r * 8;
        tile[tok][tx] = v[((size_t)(b*SS + tok0 + tok) * HK + hk) * HD + d0 + tx];
    }
    __syncthreads();
    #pragma unroll
    for (int r = 0; r < 4; r++) {
        int d = ty + r * 8;
        size_t idx = ((size_t)(b*HK + hk) * HD + d0 + d) * SS + tok0 + tx;
        vt[idx] = __float2half_rn(tile[tx][d]);
    }
}

// ---------------- mma.sync flash attention (causal, GQA rep=2) -------------
// All operands single fp16. 128 q rows/CTA, 8 warps x 16 rows, 64-key tiles.
#define KST 136                    // K/Q smem stride (halves)
#define VSTR 72                    // V^T smem stride (halves)
#define KMAT (64 * KST * 2)        // 17408 B (64-row K tile)
#define QMAT (128 * KST * 2)       // 34816 B (Q area)
#define VMAT (128 * VSTR * 2)      // 18432 B
#define ASTG (KMAT + VMAT)         // 35840 B per stage
#define ATT_SMEM (QMAT + 2 * ASTG) // 106496 B

__global__ __launch_bounds__(256, 1)
void attn_mma(const __half* __restrict__ q16, const __half* __restrict__ k16,
              const __half* __restrict__ vt16, __half* __restrict__ o16)
{
    extern __shared__ char smem[];
    const uint32_t sb = smem_u32(smem);
    const int t = threadIdx.x, lane = t & 31, w = t >> 5;
    const int b = blockIdx.z, h = blockIdx.y;
    const int qblk = (int)gridDim.x - 1 - (int)blockIdx.x;   // heavy tiles first
    const int hk = h >> 1, q0 = qblk * 128;
    const int ntiles = 2 * qblk + 2;
    const float scale = 0.08838834764831845f;

    const __half* kb_g = k16 + ((size_t)(b*SS) * HK + hk) * HD;
    const __half* vb_g = vt16 + (size_t)(b*HK + hk) * HD * SS;

    // ---- Q into dedicated area ----
    {
        const __half* qs = q16 + ((size_t)(b*SS + q0) * H + h) * HD;
        #pragma unroll
        for (int i = 0; i < 8; i++) {
            int idx = t + i * 256;            // 0..2047
            int row = idx >> 4, c = idx & 15;
            CP_ASYNC16(sb + row * (KST*2) + c * 16, qs + (size_t)row * (H*HD) + c * 8);
        }
        CP_COMMIT();
    }
    // stage 0 (kt=0)
    {
        uint32_t st = sb + QMAT;
        #pragma unroll
        for (int i = 0; i < 4; i++) {
            int idx = t + i * 256;            // 0..1023
            int row = idx >> 4, c = idx & 15;
            CP_ASYNC16(st + row * (KST*2) + c * 16, kb_g + (size_t)row * (HK*HD) + c * 8);
            int vrow = idx >> 3, vc = idx & 7;
            CP_ASYNC16(st + KMAT + vrow * (VSTR*2) + vc * 16, vb_g + (size_t)vrow * SS + vc * 8);
        }
        CP_COMMIT();
    }
    CP_WAIT1();      // Q group done
    __syncthreads();

    // extract Q fragments
    uint32_t qf[8][4];
    {
        uint32_t roff = (w * 16 + (lane & 15)) * (KST*2) + ((lane >> 4) & 1) * 16;
        #pragma unroll
        for (int ks = 0; ks < 8; ks++)
            ldsm4(qf[ks], sb + roff + ks * 32);
    }
    // stage 1 (kt=1)
    {
        uint32_t st = sb + QMAT + ASTG;
        const __half* ksh = kb_g + (size_t)64 * (HK*HD);
        #pragma unroll
        for (int i = 0; i < 4; i++) {
            int idx = t + i * 256;
            int row = idx >> 4, c = idx & 15;
            CP_ASYNC16(st + row * (KST*2) + c * 16, ksh + (size_t)row * (HK*HD) + c * 8);
            int vrow = idx >> 3, vc = idx & 7;
            CP_ASYNC16(st + KMAT + vrow * (VSTR*2) + vc * 16, vb_g + (size_t)vrow * SS + 64 + vc * 8);
        }
        CP_COMMIT();
    }

    float oacc[16][4];
    #pragma unroll
    for (int i = 0; i < 16; i++) oacc[i][0] = oacc[i][1] = oacc[i][2] = oacc[i][3] = 0.f;
    float m0 = -1e30f, m1 = -1e30f, l0 = 0.f, l1 = 0.f;

    const int gr0 = q0 + w * 16 + (lane >> 2);
    const int gc_base = (lane & 3) * 2;

    for (int kt = 0; kt < ntiles; kt++) {
        if (kt + 1 < ntiles) { CP_WAIT1(); } else { CP_WAIT0(); }
        __syncthreads();
        uint32_t st = sb + QMAT + (kt & 1) * ASTG;

        // ---- S = Q K^T ----
        float s[8][4];
        #pragma unroll
        for (int i = 0; i < 8; i++) s[i][0] = s[i][1] = s[i][2] = s[i][3] = 0.f;

        #pragma unroll
        for (int ks = 0; ks < 8; ks++) {
            uint32_t lrow = (lane & 7) + ((lane >> 4) << 3);
            uint32_t lcol = (ks * 16 + ((lane >> 3) & 1) * 8) * 2;
            #pragma unroll
            for (int p = 0; p < 4; p++) {
                uint32_t kf[4];
                ldsm4(kf, st + (p * 16 + lrow) * (KST*2) + lcol);
                mma_f16(s[2*p],   qf[ks], &kf[0]);
                mma_f16(s[2*p+1], qf[ks], &kf[2]);
            }
        }

        // ---- softmax (fp32, warp-local rows) ----
        const int kc0 = kt * 64;
        bool fullok = (kc0 + 63 <= q0 + w * 16);
        #pragma unroll
        for (int nt = 0; nt < 8; nt++) {
            if (fullok) {
                s[nt][0] *= scale; s[nt][1] *= scale; s[nt][2] *= scale; s[nt][3] *= scale;
            } else {
                int gc = kc0 + nt * 8 + gc_base;
                s[nt][0] = (gc     <= gr0    ) ? s[nt][0] * scale : -1e30f;
                s[nt][1] = (gc + 1 <= gr0    ) ? s[nt][1] * scale : -1e30f;
                s[nt][2] = (gc     <= gr0 + 8) ? s[nt][2] * scale : -1e30f;
                s[nt][3] = (gc + 1 <= gr0 + 8) ? s[nt][3] * scale : -1e30f;
            }
        }
        float mx0 = -1e30f, mx1 = -1e30f;
        #pragma unroll
        for (int nt = 0; nt < 8; nt++) {
            mx0 = fmaxf(mx0, fmaxf(s[nt][0], s[nt][1]));
            mx1 = fmaxf(mx1, fmaxf(s[nt][2], s[nt][3]));
        }
        #pragma unroll
        for (int o = 1; o <= 2; o <<= 1) {
            mx0 = fmaxf(mx0, __shfl_xor_sync(0xffffffffu, mx0, o));
            mx1 = fmaxf(mx1, __shfl_xor_sync(0xffffffffu, mx1, o));
        }
        float mn0 = fmaxf(m0, mx0), mn1 = fmaxf(m1, mx1);
        float cr0 = __expf(m0 - mn0), cr1 = __expf(m1 - mn1);
        m0 = mn0; m1 = mn1;
        #pragma unroll
        for (int nt = 0; nt < 16; nt++) {
            oacc[nt][0] *= cr0; oacc[nt][1] *= cr0;
            oacc[nt][2] *= cr1; oacc[nt][3] *= cr1;
        }

        uint32_t pf[4][4];
        float sum0 = 0.f, sum1 = 0.f;
        #pragma unroll
        for (int nt = 0; nt < 8; nt++) {
            float p0 = __expf(s[nt][0] - mn0);
            float p1 = __expf(s[nt][1] - mn0);
            float p2 = __expf(s[nt][2] - mn1);
            float p3 = __expf(s[nt][3] - mn1);
            sum0 += p0 + p1; sum1 += p2 + p3;
            int j = nt >> 1, hi2 = (nt & 1) * 2;
            pf[j][hi2]     = pack_hf2(p0, p1);
            pf[j][hi2 + 1] = pack_hf2(p2, p3);
        }
        #pragma unroll
        for (int o = 1; o <= 2; o <<= 1) {
            sum0 += __shfl_xor_sync(0xffffffffu, sum0, o);
            sum1 += __shfl_xor_sync(0xffffffffu, sum1, o);
        }
        l0 = l0 * cr0 + sum0;
        l1 = l1 * cr1 + sum1;

        // ---- O += P V ; V^T tile [128 d][64 keys] ----
        uint32_t vst = st + KMAT;
        #pragma unroll
        for (int ks = 0; ks < 4; ks++) {
            uint32_t lrow = (lane & 7) + ((lane >> 4) << 3);
            uint32_t lcol = (ks * 16 + ((lane >> 3) & 1) * 8) * 2;
            #pragma unroll
            for (int p = 0; p < 8; p++) {
                uint32_t vb[4];
                ldsm4(vb, vst + (p * 16 + lrow) * (VSTR*2) + lcol);
                mma_f16(oacc[2*p],   pf[ks], &vb[0]);
                mma_f16(oacc[2*p+1], pf[ks], &vb[2]);
            }
        }

        __syncthreads();
        // prefetch kt+2
        if (kt + 2 < ntiles) {
            uint32_t st2 = sb + QMAT + (kt & 1) * ASTG;
            int kc = (kt + 2) * 64;
            const __half* ksh = kb_g + (size_t)kc * (HK*HD);
            #pragma unroll
            for (int i = 0; i < 4; i++) {
                int idx = t + i * 256;
                int row = idx >> 4, c = idx & 15;
                CP_ASYNC16(st2 + row * (KST*2) + c * 16, ksh + (size_t)row * (HK*HD) + c * 8);
                int vrow = idx >> 3, vc = idx & 7;
                CP_ASYNC16(st2 + KMAT + vrow * (VSTR*2) + vc * 16, vb_g + (size_t)vrow * SS + kc + vc * 8);
            }
        }
        CP_COMMIT();
    }

    // ---- epilogue: normalize, write single fp16 O ----
    float inv0 = 1.f / l0, inv1 = 1.f / l1;
    size_t obase = ((size_t)(b*SS + q0 + w*16 + (lane >> 2)) * H + h) * HD;
    #pragma unroll
    for (int nt = 0; nt < 16; nt++) {
        int d = nt * 8 + gc_base;
        *(uint32_t*)(o16 + obase + d) =
            pack_hf2(oacc[nt][0] * inv0, oacc[nt][1] * inv0);
        *(uint32_t*)(o16 + obase + (size_t)8 * H * HD + d) =
            pack_hf2(oacc[nt][2] * inv1, oacc[nt][3] * inv1);
    }
}

// ---------------- launch ----------------------------------------------------
extern "C" void kernel_launch(void* const* d_in, const int* in_sizes, int n_in,
                              void* d_out, int out_size)
{
    (void)in_sizes; (void)n_in; (void)out_size;
    const float* x  = (const float*)d_in[0];
    const float* wq = (const float*)d_in[1];
    const float* wk = (const float*)d_in[2];
    const float* wv = (const float*)d_in[3];
    const float* wo = (const float*)d_in[4];
    const float* qw = (const float*)d_in[5];
    const float* kw = (const float*)d_in[6];
    float* out = (float*)d_out;

    float *q, *k, *v;
    cudaGetSymbolAddress((void**)&q, g_q);
    cudaGetSymbolAddress((void**)&k, g_k);
    cudaGetSymbolAddress((void**)&v, g_v);

    __half *x16, *wq16, *wk16, *wv16, *wo16, *o16, *q16, *k16, *vt16;
    cudaGetSymbolAddress((void**)&x16,  g_x16);
    cudaGetSymbolAddress((void**)&wq16, g_wq16); cudaGetSymbolAddress((void**)&wk16, g_wk16);
    cudaGetSymbolAddress((void**)&wv16, g_wv16); cudaGetSymbolAddress((void**)&wo16, g_wo16);
    cudaGetSymbolAddress((void**)&o16,  g_o16);  cudaGetSymbolAddress((void**)&q16,  g_q16);
    cudaGetSymbolAddress((void**)&k16,  g_k16);  cudaGetSymbolAddress((void**)&vt16, g_vt16);

    cudaFuncSetAttribute(gemm_f16, cudaFuncAttributeMaxDynamicSharedMemorySize, GEMM_SMEM);
    cudaFuncSetAttribute(gemm_qkv, cudaFuncAttributeMaxDynamicSharedMemorySize, GEMM_SMEM);
    cudaFuncSetAttribute(attn_mma, cudaFuncAttributeMaxDynamicSharedMemorySize, ATT_SMEM);

    // all fp32->fp16 conversions in one launch
    conv_all<<<(N4_TOT + 255)/256, 256>>>(x, wq, wk, wv, wo,
                                          x16, wq16, wk16, wv16, wo16);
    rope_table<<<SS, 64>>>();

    // fused QKV projections (one launch, no inter-GEMM wave quantization)
    gemm_qkv<<<1024, 256, GEMM_SMEM>>>(x16, wq16, wk16, wv16, q, k, v);

    // RMSNorm + RoPE -> single fp16
    norm_rope_f16<<<(MTOT*H )/8, 256>>>(q, q16, qw, H);
    norm_rope_f16<<<(MTOT*HK)/8, 256>>>(k, k16, kw, HK);
    transp_v16<<<dim3(SS/32, HD/32, BB*HK), 256>>>(v, vt16);

    // causal attention on tensor cores
    attn_mma<<<dim3(SS/128, H, BB), 256, ATT_SMEM>>>(q16, k16, vt16, o16);

    // output projection
    gemm_f16<<<dim3(DD/128, MTOT/128), 256, GEMM_SMEM>>>(o16, wo16, out, DD, H*HD);
}

// round 16
// speedup vs baseline: 1.0027x; 1.0027x over previous
#include <cuda_runtime.h>
#include <cuda_fp16.h>
#include <math.h>
#include <stdint.h>

#define BB 2
#define SS 2048
#define DD 2048
#define H 16
#define HK 8
#define HD 128
#define MTOT (BB*SS)   // 4096

// ---------------- scratch (allocation-free: device globals) ----------------
__device__ float g_q[(size_t)MTOT * H * HD];
__device__ float g_k[(size_t)MTOT * HK * HD];
__device__ float g_v[(size_t)MTOT * HK * HD];
__device__ float g_cos[SS * 64];
__device__ float g_sin[SS * 64];

__device__ __align__(16) __half g_x16[(size_t)MTOT * DD];
__device__ __align__(16) __half g_wq16[(size_t)(H*HD) * DD];
__device__ __align__(16) __half g_wk16[(size_t)(HK*HD) * DD];
__device__ __align__(16) __half g_wv16[(size_t)(HK*HD) * DD];
__device__ __align__(16) __half g_wo16[(size_t)DD * (H*HD)];
__device__ __align__(16) __half g_o16[(size_t)MTOT * (H*HD)];
__device__ __align__(16) __half g_q16[(size_t)MTOT * H * HD];
__device__ __align__(16) __half g_k16[(size_t)MTOT * HK * HD];
__device__ __align__(16) __half g_vt16[(size_t)MTOT * HK * HD];  // [b][hk][d][tok]

// ---------------- asm helpers ----------------------------------------------
__device__ __forceinline__ uint32_t smem_u32(const void* p) {
    uint32_t a;
    asm("{ .reg .u64 t; cvta.to.shared.u64 t, %1; cvt.u32.u64 %0, t; }" : "=r"(a) : "l"(p));
    return a;
}

#define CP_ASYNC16(dst, src) \
    asm volatile("cp.async.cg.shared.global [%0], [%1], 16;" :: "r"(dst), "l"(src))
#define CP_COMMIT() asm volatile("cp.async.commit_group;" ::: "memory")
#define CP_WAIT2()  asm volatile("cp.async.wait_group 2;" ::: "memory")
#define CP_WAIT1()  asm volatile("cp.async.wait_group 1;" ::: "memory")
#define CP_WAIT0()  asm volatile("cp.async.wait_group 0;" ::: "memory")

__device__ __forceinline__ void ldsm4(uint32_t* r, uint32_t a) {
    asm volatile("ldmatrix.sync.aligned.m8n8.x4.shared.b16 {%0,%1,%2,%3}, [%4];"
        : "=r"(r[0]), "=r"(r[1]), "=r"(r[2]), "=r"(r[3]) : "r"(a));
}
__device__ __forceinline__ void ldsm2(uint32_t* r, uint32_t a) {
    asm volatile("ldmatrix.sync.aligned.m8n8.x2.shared.b16 {%0,%1}, [%2];"
        : "=r"(r[0]), "=r"(r[1]) : "r"(a));
}
__device__ __forceinline__ void mma_f16(float* c, const uint32_t* a, const uint32_t* b) {
    asm volatile("mma.sync.aligned.m16n8k16.row.col.f32.f16.f16.f32 "
        "{%0,%1,%2,%3}, {%4,%5,%6,%7}, {%8,%9}, {%0,%1,%2,%3};"
        : "+f"(c[0]), "+f"(c[1]), "+f"(c[2]), "+f"(c[3])
        : "r"(a[0]), "r"(a[1]), "r"(a[2]), "r"(a[3]), "r"(b[0]), "r"(b[1]));
}

__device__ __forceinline__ uint32_t pack_hf2(float a, float b) {
    __half2 t;
    t.x = __float2half_rn(a);
    t.y = __float2half_rn(b);
    return *(uint32_t*)&t;
}

// --------- single-pass fp16 GEMM body: C = A * B^T -------------------------
// A (M,K) fp16, W (N,K) fp16, C (M,N) fp32. CTA 128x128, BK=32, 256 thr.
// 4-stage cp.async pipeline, smem stride 40 halves (conflict-free ldmatrix).
#define SST 40
#define MATB (128 * SST * 2)      // 10240 B per matrix
#define STG1 (2 * MATB)           // 20480 B per stage (A, B)
#define GEMM_SMEM (4 * STG1)      // 81920 B  -> 2 CTAs/SM

__device__ __forceinline__ void gemm_load_stage(
    uint32_t sbase, int slot,
    const __half* __restrict__ A, const __half* __restrict__ B,
    int m0, int n0, int K, int k0, int t)
{
    uint32_t st = sbase + slot * STG1;
    const __half* gp[2] = { A + (size_t)m0 * K + k0, B + (size_t)n0 * K + k0 };
    #pragma unroll
    for (int mat = 0; mat < 2; mat++) {
        #pragma unroll
        for (int h = 0; h < 2; h++) {
            int c = t + h * 256;          // 0..511
            int row = c >> 2, col16 = c & 3;
            uint32_t dst = st + mat * MATB + row * (SST*2) + col16 * 16;
            const __half* src = gp[mat] + (size_t)row * K + col16 * 8;
            CP_ASYNC16(dst, src);
        }
    }
}

__device__ __forceinline__ void gemm_body(
    uint32_t sb, const __half* __restrict__ A, const __half* __restrict__ B,
    float* __restrict__ C, int N, int K, int m0, int n0, int t)
{
    const int lane = t & 31, wid = t >> 5;
    const int warp_m = wid >> 2;
    const int warp_n = wid & 3;
    const int niter = K >> 5;

    float acc[4][4][4];
    #pragma unroll
    for (int i = 0; i < 4; i++)
        #pragma unroll
        for (int j = 0; j < 4; j++)
            acc[i][j][0] = acc[i][j][1] = acc[i][j][2] = acc[i][j][3] = 0.f;

    #pragma unroll
    for (int s = 0; s < 3; s++) {
        if (s < niter) gemm_load_stage(sb, s, A, B, m0, n0, K, s * 32, t);
        CP_COMMIT();
    }

    const int arow = warp_m * 64 + (lane & 15);
    const int acolh = (lane >> 4) * 8;
    const int l2 = lane & 15;
    const int brow = warp_n * 32 + (l2 & 7);
    const int bcolh = (l2 >> 3) * 8;

    for (int it = 0; it < niter; it++) {
        int ps = it + 3;
        if (ps < niter)
            gemm_load_stage(sb, ps & 3, A, B, m0, n0, K, ps * 32, t);
        CP_COMMIT();
        CP_WAIT2();
        __syncthreads();

        uint32_t st = sb + (it & 3) * STG1;
        #pragma unroll
        for (int ks = 0; ks < 2; ks++) {
            uint32_t af[4][4], bf[4][2];
            #pragma unroll
            for (int mt = 0; mt < 4; mt++) {
                uint32_t off = ((arow + mt * 16) * SST + ks * 16 + acolh) * 2;
                ldsm4(af[mt], st + off);
            }
            #pragma unroll
            for (int nt = 0; nt < 4; nt++) {
                uint32_t off = ((brow + nt * 8) * SST + ks * 16 + bcolh) * 2;
                ldsm2(bf[nt], st + MATB + off);
            }
            #pragma unroll
            for (int mt = 0; mt < 4; mt++)
                #pragma unroll
                for (int nt = 0; nt < 4; nt++)
                    mma_f16(acc[mt][nt], af[mt], bf[nt]);
        }
        __syncthreads();
    }

    const int r0 = lane >> 2, c0 = (lane & 3) * 2;
    #pragma unroll
    for (int mt = 0; mt < 4; mt++) {
        #pragma unroll
        for (int nt = 0; nt < 4; nt++) {
            int row = m0 + warp_m * 64 + mt * 16 + r0;
            int col = n0 + warp_n * 32 + nt * 8 + c0;
            *(float2*)(C + (size_t)row * N + col) =
                make_float2(acc[mt][nt][0], acc[mt][nt][1]);
            *(float2*)(C + (size_t)(row + 8) * N + col) =
                make_float2(acc[mt][nt][2], acc[mt][nt][3]);
        }
    }
}

// out-projection (single GEMM)
__global__ __launch_bounds__(256, 2)
void gemm_f16(const __half* __restrict__ A, const __half* __restrict__ B,
              float* __restrict__ C, int N, int K)
{
    extern __shared__ char smem[];
    gemm_body(smem_u32(smem), A, B, C, N, K,
              blockIdx.y * 128, blockIdx.x * 128, threadIdx.x);
}

// fused QKV: one launch, 1024 CTAs decode {Q:512, K:256, V:256}
__global__ __launch_bounds__(256, 2)
void gemm_qkv(const __half* __restrict__ x16,
              const __half* __restrict__ wq16, const __half* __restrict__ wk16,
              const __half* __restrict__ wv16,
              float* __restrict__ q, float* __restrict__ k, float* __restrict__ v)
{
    extern __shared__ char smem[];
    int bid = blockIdx.x;
    const __half* B;
    float* C;
    int N, m0, n0;
    if (bid < 512) {                 // Q: 16 n-tiles x 32 m-tiles
        B = wq16; C = q; N = H*HD;
        n0 = (bid & 15) * 128; m0 = (bid >> 4) * 128;
    } else if (bid < 768) {          // K: 8 x 32
        int b2 = bid - 512;
        B = wk16; C = k; N = HK*HD;
        n0 = (b2 & 7) * 128; m0 = (b2 >> 3) * 128;
    } else {                         // V: 8 x 32
        int b2 = bid - 768;
        B = wv16; C = v; N = HK*HD;
        n0 = (b2 & 7) * 128; m0 = (b2 >> 3) * 128;
    }
    gemm_body(smem_u32(smem), x16, B, C, N, DD, m0, n0, threadIdx.x);
}

// ------- fused fp32 -> fp16 conversion of all 5 tensors in one launch ------
#define N4_X  (MTOT*DD/4)          // 2097152
#define N4_WQ (H*HD*DD/4)          // 1048576
#define N4_WK (HK*HD*DD/4)         //  524288
#define N4_WV (HK*HD*DD/4)         //  524288
#define N4_WO (DD*H*HD/4)          // 1048576
#define N4_TOT (N4_X + N4_WQ + N4_WK + N4_WV + N4_WO)

__global__ __launch_bounds__(256)
void conv_all(const float* __restrict__ x,  const float* __restrict__ wq,
              const float* __restrict__ wk, const float* __restrict__ wv,
              const float* __restrict__ wo,
              __half* __restrict__ x16,  __half* __restrict__ wq16,
              __half* __restrict__ wk16, __half* __restrict__ wv16,
              __half* __restrict__ wo16)
{
    int i = blockIdx.x * blockDim.x + threadIdx.x;
    if (i >= N4_TOT) return;
    const float* src;
    __half* dst;
    int j = i;
    if (j < N4_X)                        { src = x;  dst = x16; }
    else if ((j -= N4_X)  < N4_WQ)       { src = wq; dst = wq16; }
    else if ((j -= N4_WQ) < N4_WK)       { src = wk; dst = wk16; }
    else if ((j -= N4_WK) < N4_WV)       { src = wv; dst = wv16; }
    else { j -= N4_WV;                     src = wo; dst = wo16; }
    float4 vv = ((const float4*)src)[j];
    __half2 p0, p1;
    p0.x = __float2half_rn(vv.x); p0.y = __float2half_rn(vv.y);
    p1.x = __float2half_rn(vv.z); p1.y = __float2half_rn(vv.w);
    ((__half2*)(dst + (size_t)j * 4))[0] = p0;
    ((__half2*)(dst + (size_t)j * 4))[1] = p1;
}

// ---------------- RoPE table ------------------------------------------------
__global__ void rope_table()
{
    int s = blockIdx.x;
    int j = threadIdx.x;
    double invd = pow(1.0e6, -(double)j / 64.0);
    float  ang  = (float)s * (float)invd;
    float  c, sn;
    sincosf(ang, &sn, &c);
    g_cos[s*64 + j] = c;
    g_sin[s*64 + j] = sn;
}

// -------- fused RMSNorm + RoPE -> single fp16 ------------------------------
__global__ __launch_bounds__(256)
void norm_rope_f16(const float* __restrict__ buf, __half* __restrict__ outh,
                   const float* __restrict__ w, int nheads)
{
    int gw   = (blockIdx.x * blockDim.x + threadIdx.x) >> 5;
    int lane = threadIdx.x & 31;
    int m = gw / nheads;
    int h = gw - m * nheads;
    int s = m & (SS - 1);

    size_t base = ((size_t)m * nheads + h) * HD + lane * 4;
    float4 v = *(const float4*)(buf + base);
    float ss = v.x*v.x + v.y*v.y + v.z*v.z + v.w*v.w;
    #pragma unroll
    for (int o = 16; o; o >>= 1) ss += __shfl_xor_sync(0xffffffffu, ss, o);
    float r = rsqrtf(ss * (1.f/128.f) + 1e-6f);

    const float4 wv = *(const float4*)(w + lane*4);
    v.x *= r * wv.x; v.y *= r * wv.y; v.z *= r * wv.z; v.w *= r * wv.w;

    float4 pr;
    pr.x = __shfl_xor_sync(0xffffffffu, v.x, 16);
    pr.y = __shfl_xor_sync(0xffffffffu, v.y, 16);
    pr.z = __shfl_xor_sync(0xffffffffu, v.z, 16);
    pr.w = __shfl_xor_sync(0xffffffffu, v.w, 16);

    int jbase = (lane & 15) * 4;
    const float* cb = g_cos + s*64 + jbase;
    const float* sb = g_sin + s*64 + jbase;
    float sgn = (lane < 16) ? -1.f : 1.f;

    float o0 = v.x * cb[0] + sgn * pr.x * sb[0];
    float o1 = v.y * cb[1] + sgn * pr.y * sb[1];
    float o2 = v.z * cb[2] + sgn * pr.z * sb[2];
    float o3 = v.w * cb[3] + sgn * pr.w * sb[3];

    __half2 hp0, hp1;
    hp0.x = __float2half_rn(o0); hp0.y = __float2half_rn(o1);
    hp1.x = __float2half_rn(o2); hp1.y = __float2half_rn(o3);
    ((__half2*)(outh + base))[0] = hp0;
    ((__half2*)(outh + base))[1] = hp1;
}

// ---- V transpose: [tok][hk][d] fp32 -> [b][hk][d][tok] fp16 ---------------
__global__ __launch_bounds__(256)
void transp_v16(const float* __restrict__ v, __half* __restrict__ vt)
{
    __shared__ float tile[32][33];
    int t = threadIdx.x;
    int tx = t & 31, ty = t >> 5;
    int tok0 = blockIdx.x * 32, d0 = blockIdx.y * 32;
    int bh = blockIdx.z;
    int b = bh >> 3, hk = bh & 7;

    #pragma unroll
    for (int r = 0; r < 4; r++) {
        int tok = ty + r * 8;
        tile[tok][tx] = v[((size_t)(b*SS + tok0 + tok) * HK + hk) * HD + d0 + tx];
    }
    __syncthreads();
    #pragma unroll
    for (int r = 0; r < 4; r++) {
        int d = ty + r * 8;
        size_t idx = ((size_t)(b*HK + hk) * HD + d0 + d) * SS + tok0 + tx;
        vt[idx] = __float2half_rn(tile[tx][d]);
    }
}

// ---------------- mma.sync flash attention (causal, GQA rep=2) -------------
// All operands single fp16. 128 q rows/CTA, 8 warps x 16 rows, 64-key tiles.
#define KST 136                    // K/Q smem stride (halves)
#define VSTR 72                    // V^T smem stride (halves)
#define KMAT (64 * KST * 2)        // 17408 B (64-row K tile)
#define QMAT (128 * KST * 2)       // 34816 B (Q area)
#define VMAT (128 * VSTR * 2)      // 18432 B
#define ASTG (KMAT + VMAT)         // 35840 B per stage
#define ATT_SMEM (QMAT + 2 * ASTG) // 106496 B

__global__ __launch_bounds__(256, 1)
void attn_mma(const __half* __restrict__ q16, const __half* __restrict__ k16,
              const __half* __restrict__ vt16, __half* __restrict__ o16)
{
    extern __shared__ char smem[];
    const uint32_t sb = smem_u32(smem);
    const int t = threadIdx.x, lane = t & 31, w = t >> 5;
    const int b = blockIdx.z, h = blockIdx.y;
    const int qblk = (int)gridDim.x - 1 - (int)blockIdx.x;   // heavy tiles first
    const int hk = h >> 1, q0 = qblk * 128;
    const int ntiles = 2 * qblk + 2;
    const float scale = 0.08838834764831845f;

    const __half* kb_g = k16 + ((size_t)(b*SS) * HK + hk) * HD;
    const __half* vb_g = vt16 + (size_t)(b*HK + hk) * HD * SS;

    // ---- Q into dedicated area ----
    {
        const __half* qs = q16 + ((size_t)(b*SS + q0) * H + h) * HD;
        #pragma unroll
        for (int i = 0; i < 8; i++) {
            int idx = t + i * 256;            // 0..2047
            int row = idx >> 4, c = idx & 15;
            CP_ASYNC16(sb + row * (KST*2) + c * 16, qs + (size_t)row * (H*HD) + c * 8);
        }
        CP_COMMIT();
    }
    // stage 0 (kt=0)
    {
        uint32_t st = sb + QMAT;
        #pragma unroll
        for (int i = 0; i < 4; i++) {
            int idx = t + i * 256;            // 0..1023
            int row = idx >> 4, c = idx & 15;
            CP_ASYNC16(st + row * (KST*2) + c * 16, kb_g + (size_t)row * (HK*HD) + c * 8);
            int vrow = idx >> 3, vc = idx & 7;
            CP_ASYNC16(st + KMAT + vrow * (VSTR*2) + vc * 16, vb_g + (size_t)vrow * SS + vc * 8);
        }
        CP_COMMIT();
    }
    CP_WAIT1();      // Q group done
    __syncthreads();

    // extract Q fragments
    uint32_t qf[8][4];
    {
        uint32_t roff = (w * 16 + (lane & 15)) * (KST*2) + ((lane >> 4) & 1) * 16;
        #pragma unroll
        for (int ks = 0; ks < 8; ks++)
            ldsm4(qf[ks], sb + roff + ks * 32);
    }
    // stage 1 (kt=1)
    {
        uint32_t st = sb + QMAT + ASTG;
        const __half* ksh = kb_g + (size_t)64 * (HK*HD);
        #pragma unroll
        for (int i = 0; i < 4; i++) {
            int idx = t + i * 256;
            int row = idx >> 4, c = idx & 15;
            CP_ASYNC16(st + row * (KST*2) + c * 16, ksh + (size_t)row * (HK*HD) + c * 8);
            int vrow = idx >> 3, vc = idx & 7;
            CP_ASYNC16(st + KMAT + vrow * (VSTR*2) + vc * 16, vb_g + (size_t)vrow * SS + 64 + vc * 8);
        }
        CP_COMMIT();
    }

    float oacc[16][4];
    #pragma unroll
    for (int i = 0; i < 16; i++) oacc[i][0] = oacc[i][1] = oacc[i][2] = oacc[i][3] = 0.f;
    float m0 = -1e30f, m1 = -1e30f, l0 = 0.f, l1 = 0.f;

    const int gr0 = q0 + w * 16 + (lane >> 2);
    const int gc_base = (lane & 3) * 2;

    for (int kt = 0; kt < ntiles; kt++) {
        if (kt + 1 < ntiles) { CP_WAIT1(); } else { CP_WAIT0(); }
        __syncthreads();
        uint32_t st = sb + QMAT + (kt & 1) * ASTG;

        // ---- S = Q K^T ----
        float s[8][4];
        #pragma unroll
        for (int i = 0; i < 8; i++) s[i][0] = s[i][1] = s[i][2] = s[i][3] = 0.f;

        #pragma unroll
        for (int ks = 0; ks < 8; ks++) {
            uint32_t lrow = (lane & 7) + ((lane >> 4) << 3);
            uint32_t lcol = (ks * 16 + ((lane >> 3) & 1) * 8) * 2;
            #pragma unroll
            for (int p = 0; p < 4; p++) {
                uint32_t kf[4];
                ldsm4(kf, st + (p * 16 + lrow) * (KST*2) + lcol);
                mma_f16(s[2*p],   qf[ks], &kf[0]);
                mma_f16(s[2*p+1], qf[ks], &kf[2]);
            }
        }

        // ---- softmax (fp32, warp-local rows) ----
        const int kc0 = kt * 64;
        bool fullok = (kc0 + 63 <= q0 + w * 16);
        #pragma unroll
        for (int nt = 0; nt < 8; nt++) {
            if (fullok) {
                s[nt][0] *= scale; s[nt][1] *= scale; s[nt][2] *= scale; s[nt][3] *= scale;
            } else {
                int gc = kc0 + nt * 8 + gc_base;
                s[nt][0] = (gc     <= gr0    ) ? s[nt][0] * scale : -1e30f;
                s[nt][1] = (gc + 1 <= gr0    ) ? s[nt][1] * scale : -1e30f;
                s[nt][2] = (gc     <= gr0 + 8) ? s[nt][2] * scale : -1e30f;
                s[nt][3] = (gc + 1 <= gr0 + 8) ? s[nt][3] * scale : -1e30f;
            }
        }
        float mx0 = -1e30f, mx1 = -1e30f;
        #pragma unroll
        for (int nt = 0; nt < 8; nt++) {
            mx0 = fmaxf(mx0, fmaxf(s[nt][0], s[nt][1]));
            mx1 = fmaxf(mx1, fmaxf(s[nt][2], s[nt][3]));
        }
        #pragma unroll
        for (int o = 1; o <= 2; o <<= 1) {
            mx0 = fmaxf(mx0, __shfl_xor_sync(0xffffffffu, mx0, o));
            mx1 = fmaxf(mx1, __shfl_xor_sync(0xffffffffu, mx1, o));
        }
        float mn0 = fmaxf(m0, mx0), mn1 = fmaxf(m1, mx1);
        float cr0 = __expf(m0 - mn0), cr1 = __expf(m1 - mn1);
        m0 = mn0; m1 = mn1;
        #pragma unroll
        for (int nt = 0; nt < 16; nt++) {
            oacc[nt][0] *= cr0; oacc[nt][1] *= cr0;
            oacc[nt][2] *= cr1; oacc[nt][3] *= cr1;
        }

        uint32_t pf[4][4];
        float sum0 = 0.f, sum1 = 0.f;
        #pragma unroll
        for (int nt = 0; nt < 8; nt++) {
            float p0 = __expf(s[nt][0] - mn0);
            float p1 = __expf(s[nt][1] - mn0);
            float p2 = __expf(s[nt][2] - mn1);
            float p3 = __expf(s[nt][3] - mn1);
            sum0 += p0 + p1; sum1 += p2 + p3;
            int j = nt >> 1, hi2 = (nt & 1) * 2;
            pf[j][hi2]     = pack_hf2(p0, p1);
            pf[j][hi2 + 1] = pack_hf2(p2, p3);
        }
        #pragma unroll
        for (int o = 1; o <= 2; o <<= 1) {
            sum0 += __shfl_xor_sync(0xffffffffu, sum0, o);
            sum1 += __shfl_xor_sync(0xffffffffu, sum1, o);
        }
        l0 = l0 * cr0 + sum0;
        l1 = l1 * cr1 + sum1;

        // ---- O += P V ; V^T tile [128 d][64 keys] ----
        uint32_t vst = st + KMAT;
        #pragma unroll
        for (int ks = 0; ks < 4; ks++) {
            uint32_t lrow = (lane & 7) + ((lane >> 4) << 3);
            uint32_t lcol = (ks * 16 + ((lane >> 3) & 1) * 8) * 2;
            #pragma unroll
            for (int p = 0; p < 8; p++) {
                uint32_t vb[4];
                ldsm4(vb, vst + (p * 16 + lrow) * (VSTR*2) + lcol);
                mma_f16(oacc[2*p],   pf[ks], &vb[0]);
                mma_f16(oacc[2*p+1], pf[ks], &vb[2]);
            }
        }

        __syncthreads();
        // prefetch kt+2
        if (kt + 2 < ntiles) {
            uint32_t st2 = sb + QMAT + (kt & 1) * ASTG;
            int kc = (kt + 2) * 64;
            const __half* ksh = kb_g + (size_t)kc * (HK*HD);
            #pragma unroll
            for (int i = 0; i < 4; i++) {
                int idx = t + i * 256;
                int row = idx >> 4, c = idx & 15;
                CP_ASYNC16(st2 + row * (KST*2) + c * 16, ksh + (size_t)row * (HK*HD) + c * 8);
                int vrow = idx >> 3, vc = idx & 7;
                CP_ASYNC16(st2 + KMAT + vrow * (VSTR*2) + vc * 16, vb_g + (size_t)vrow * SS + kc + vc * 8);
            }
        }
        CP_COMMIT();
    }

    // ---- epilogue: normalize, write single fp16 O ----
    float inv0 = 1.f / l0, inv1 = 1.f / l1;
    size_t obase = ((size_t)(b*SS + q0 + w*16 + (lane >> 2)) * H + h) * HD;
    #pragma unroll
    for (int nt = 0; nt < 16; nt++) {
        int d = nt * 8 + gc_base;
        *(uint32_t*)(o16 + obase + d) =
            pack_hf2(oacc[nt][0] * inv0, oacc[nt][1] * inv0);
        *(uint32_t*)(o16 + obase + (size_t)8 * H * HD + d) =
            pack_hf2(oacc[nt][2] * inv1, oacc[nt][3] * inv1);
    }
}

// ---------------- launch ----------------------------------------------------
extern "C" void kernel_launch(void* const* d_in, const int* in_sizes, int n_in,
                              void* d_out, int out_size)
{
    (void)in_sizes; (void)n_in; (void)out_size;
    const float* x  = (const float*)d_in[0];
    const float* wq = (const float*)d_in[1];
    const float* wk = (const float*)d_in[2];
    const float* wv = (const float*)d_in[3];
    const float* wo = (const float*)d_in[4];
    const float* qw = (const float*)d_in[5];
    const float* kw = (const float*)d_in[6];
    float* out = (float*)d_out;

    float *q, *k, *v;
    cudaGetSymbolAddress((void**)&q, g_q);
    cudaGetSymbolAddress((void**)&k, g_k);
    cudaGetSymbolAddress((void**)&v, g_v);

    __half *x16, *wq16, *wk16, *wv16, *wo16, *o16, *q16, *k16, *vt16;
    cudaGetSymbolAddress((void**)&x16,  g_x16);
    cudaGetSymbolAddress((void**)&wq16, g_wq16); cudaGetSymbolAddress((void**)&wk16, g_wk16);
    cudaGetSymbolAddress((void**)&wv16, g_wv16); cudaGetSymbolAddress((void**)&wo16, g_wo16);
    cudaGetSymbolAddress((void**)&o16,  g_o16);  cudaGetSymbolAddress((void**)&q16,  g_q16);
    cudaGetSymbolAddress((void**)&k16,  g_k16);  cudaGetSymbolAddress((void**)&vt16, g_vt16);

    cudaFuncSetAttribute(gemm_f16, cudaFuncAttributeMaxDynamicSharedMemorySize, GEMM_SMEM);
    cudaFuncSetAttribute(gemm_qkv, cudaFuncAttributeMaxDynamicSharedMemorySize, GEMM_SMEM);
    cudaFuncSetAttribute(attn_mma, cudaFuncAttributeMaxDynamicSharedMemorySize, ATT_SMEM);

    // all fp32->fp16 conversions in one launch
    conv_all<<<(N4_TOT + 255)/256, 256>>>(x, wq, wk, wv, wo,
                                          x16, wq16, wk16, wv16, wo16);
    rope_table<<<SS, 64>>>();

    // fused QKV projections (one launch, no inter-GEMM wave quantization)
    gemm_qkv<<<1024, 256, GEMM_SMEM>>>(x16, wq16, wk16, wv16, q, k, v);

    // RMSNorm + RoPE -> single fp16
    norm_rope_f16<<<(MTOT*H )/8, 256>>>(q, q16, qw, H);
    norm_rope_f16<<<(MTOT*HK)/8, 256>>>(k, k16, kw, HK);
    transp_v16<<<dim3(SS/32, HD/32, BB*HK), 256>>>(v, vt16);

    // causal attention on tensor cores
    attn_mma<<<dim3(SS/128, H, BB), 256, ATT_SMEM>>>(q16, k16, vt16, o16);

    // output projection
    gemm_f16<<<dim3(DD/128, MTOT/128), 256, GEMM_SMEM>>>(o16, wo16, out, DD, H*HD);
}